// round 8
// baseline (speedup 1.0000x reference)
#include <cuda_runtime.h>
#include <cooperative_groups.h>
#include <cstdint>

namespace cg = cooperative_groups;

// Harmonic lattice potential — R7: single cooperative persistent kernel.
//   inputs: pos (N,3) f32, edge_index (2,E) int32, batch (N,) int32 (sorted)
//   output: energy (64,) f32 ++ forces (N,3) f32
//
// R7 vs R3 (60.1us): fuse prep / edge / finalize into ONE kernel with two
// grid.sync()s. Deletes 2 launch overheads + inter-kernel gaps (~6-8us of
// fixed cost around a ~50us edge phase). Edge body identical to R3
// (4 edges/thread proved optimal: R6's 8/thread and R2's grid-stride both
// regressed). Grid = 2 CTAs/SM fixed (296x256) for guaranteed co-residency.

#define R0F 1.0f
#define NUM_GRAPHS 64
#define MAXN 131072
#define NBLOCKS 296
#define NTHREADS 256

__device__ float4 g_acc[MAXN];    // force.xyz + energy.w accumulator
__device__ float4 g_pos4[MAXN];   // packed positions

__device__ __forceinline__ void red_add_v4(float4* addr, float a, float b, float c, float d) {
    asm volatile("red.global.add.v4.f32 [%0], {%1, %2, %3, %4};"
                 :: "l"(addr), "f"(a), "f"(b), "f"(c), "f"(d));
}

__device__ __forceinline__ void do_edge(int i, int j, const float4& pi, const float4& pj) {
    float dx = pi.x - pj.x;
    float dy = pi.y - pj.y;
    float dz = pi.z - pj.z;
    float dd = fmaf(dx, dx, fmaf(dy, dy, dz * dz));
    float rinv = rsqrtf(fmaxf(dd, 1e-40f));
    float d = dd * rinv;                  // = sqrt(dd); 0 when dd==0
    float delta = d - R0F;                // K = 1
    float e = 0.5f * delta * delta;
    float s = delta * rinv;               // dx==0 when dd==0 -> force 0
    float fx = s * dx, fy = s * dy, fz = s * dz;
    red_add_v4(&g_acc[i], -fx, -fy, -fz, e);
    red_add_v4(&g_acc[j],  fx,  fy,  fz, 0.f);
}

__global__ void __launch_bounds__(NTHREADS)
fused_kernel(const float* __restrict__ pos,
             const int* __restrict__ ei,
             const int* __restrict__ batch,
             float* __restrict__ out,
             int N, int E) {
    cg::grid_group grid = cg::this_grid();
    const int gtid = blockIdx.x * NTHREADS + threadIdx.x;
    const int gstride = NBLOCKS * NTHREADS;

    // ---- Phase A: pack positions, zero accumulators + energy slots ----
    for (int t = gtid; t < N; t += gstride) {
        g_acc[t]  = make_float4(0.f, 0.f, 0.f, 0.f);
        g_pos4[t] = make_float4(__ldg(&pos[3 * t]), __ldg(&pos[3 * t + 1]),
                                __ldg(&pos[3 * t + 2]), 0.f);
    }
    if (gtid < NUM_GRAPHS) out[gtid] = 0.f;

    grid.sync();

    // ---- Phase B: edges, 4 per iteration (int4 index loads) ----
    {
        int Q = E >> 2;                       // full quads
        const int4* ia = (const int4*)ei;
        const int4* ja = (const int4*)(ei + E);
        for (int q = gtid; q < Q; q += gstride) {
            int4 iv = __ldg(&ia[q]);
            int4 jv = __ldg(&ja[q]);
            int is[4] = {iv.x, iv.y, iv.z, iv.w};
            int js[4] = {jv.x, jv.y, jv.z, jv.w};

            float4 pi[4], pj[4];
#pragma unroll
            for (int k = 0; k < 4; k++) {
                pi[k] = __ldg(&g_pos4[is[k]]);
                pj[k] = __ldg(&g_pos4[js[k]]);
            }
#pragma unroll
            for (int k = 0; k < 4; k++)
                do_edge(is[k], js[k], pi[k], pj[k]);
        }
        // remainder edges (E % 4)
        for (int e = (Q << 2) + gtid; e < E; e += gstride) {
            int i = __ldg(&ei[e]);
            int j = __ldg(&ei[E + e]);
            do_edge(i, j, __ldg(&g_pos4[i]), __ldg(&g_pos4[j]));
        }
    }

    grid.sync();

    // ---- Phase C: write forces, bin energies by (sorted) batch ----
    __shared__ float ebins[NUM_GRAPHS];
    int t0 = threadIdx.x;
    if (t0 < NUM_GRAPHS) ebins[t0] = 0.f;
    __syncthreads();

    for (int n = gtid; n < N; n += gstride) {
        float4 a = g_acc[n];
        out[NUM_GRAPHS + 3 * n + 0] = a.x;
        out[NUM_GRAPHS + 3 * n + 1] = a.y;
        out[NUM_GRAPHS + 3 * n + 2] = a.z;
        atomicAdd(&ebins[__ldg(&batch[n])], a.w);
    }
    __syncthreads();
    if (t0 < NUM_GRAPHS) {
        float v = ebins[t0];
        if (v != 0.f) atomicAdd(&out[t0], v);
    }
}

extern "C" void kernel_launch(void* const* d_in, const int* in_sizes, int n_in,
                              void* d_out, int out_size) {
    const float* pos   = (const float*)d_in[0];
    const int*   ei    = (const int*)d_in[1];
    const int*   batch = (const int*)d_in[2];
    float* out = (float*)d_out;

    int N = in_sizes[0] / 3;
    int E = in_sizes[1] / 2;

    cudaLaunchConfig_t cfg = {};
    cfg.gridDim = dim3(NBLOCKS);
    cfg.blockDim = dim3(NTHREADS);
    cfg.dynamicSmemBytes = 0;
    cfg.stream = 0;
    cudaLaunchAttribute attr[1];
    attr[0].id = cudaLaunchAttributeCooperative;
    attr[0].val.cooperative = 1;
    cfg.attrs = attr;
    cfg.numAttrs = 1;
    cudaLaunchKernelEx(&cfg, fused_kernel, pos, ei, batch, out, N, E);
}

// round 9
// speedup vs baseline: 1.0350x; 1.0350x over previous
#include <cuda_runtime.h>
#include <cooperative_groups.h>
#include <cstdint>

namespace cg = cooperative_groups;

// Harmonic lattice potential — R8: cooperative fused kernel, occupancy-sized grid.
//   inputs: pos (N,3) f32, edge_index (2,E) int32, batch (N,) int32 (sorted)
//   output: energy (64,) f32 ++ forces (N,3) f32
//
// R8 vs R7 (81.3us, failed): R7 pinned 2 CTAs/SM (16 warps, occ 24%) and the
// latency-bound edge phase starved. R8 sizes the cooperative grid via the
// occupancy API (38 regs -> 6 CTAs/SM -> 48 warps/SM, same residency as the
// R3 baseline's edge kernel) while keeping the fusion win (no 2nd/3rd launch
// overhead, no inter-kernel gaps). Edge body = R3's proven 4 edges/thread.

#define R0F 1.0f
#define NUM_GRAPHS 64
#define MAXN 131072
#define NTHREADS 256

__device__ float4 g_acc[MAXN];    // force.xyz + energy.w accumulator
__device__ float4 g_pos4[MAXN];   // packed positions

__device__ __forceinline__ void red_add_v4(float4* addr, float a, float b, float c, float d) {
    asm volatile("red.global.add.v4.f32 [%0], {%1, %2, %3, %4};"
                 :: "l"(addr), "f"(a), "f"(b), "f"(c), "f"(d));
}

__device__ __forceinline__ void do_edge(int i, int j, const float4& pi, const float4& pj) {
    float dx = pi.x - pj.x;
    float dy = pi.y - pj.y;
    float dz = pi.z - pj.z;
    float dd = fmaf(dx, dx, fmaf(dy, dy, dz * dz));
    float rinv = rsqrtf(fmaxf(dd, 1e-40f));
    float d = dd * rinv;                  // = sqrt(dd); 0 when dd==0
    float delta = d - R0F;                // K = 1
    float e = 0.5f * delta * delta;
    float s = delta * rinv;               // dx==0 when dd==0 -> force 0
    float fx = s * dx, fy = s * dy, fz = s * dz;
    red_add_v4(&g_acc[i], -fx, -fy, -fz, e);
    red_add_v4(&g_acc[j],  fx,  fy,  fz, 0.f);
}

__global__ void __launch_bounds__(NTHREADS)
fused_kernel(const float* __restrict__ pos,
             const int* __restrict__ ei,
             const int* __restrict__ batch,
             float* __restrict__ out,
             int N, int E) {
    cg::grid_group grid = cg::this_grid();
    const int gtid = blockIdx.x * NTHREADS + threadIdx.x;
    const int gstride = gridDim.x * NTHREADS;

    // ---- Phase A: pack positions, zero accumulators + energy slots ----
    for (int t = gtid; t < N; t += gstride) {
        g_acc[t]  = make_float4(0.f, 0.f, 0.f, 0.f);
        g_pos4[t] = make_float4(__ldg(&pos[3 * t]), __ldg(&pos[3 * t + 1]),
                                __ldg(&pos[3 * t + 2]), 0.f);
    }
    if (gtid < NUM_GRAPHS) out[gtid] = 0.f;

    grid.sync();

    // ---- Phase B: edges, 4 per iteration (int4 index loads) ----
    {
        int Q = E >> 2;                       // full quads
        const int4* ia = (const int4*)ei;
        const int4* ja = (const int4*)(ei + E);
        for (int q = gtid; q < Q; q += gstride) {
            int4 iv = __ldg(&ia[q]);
            int4 jv = __ldg(&ja[q]);
            int is[4] = {iv.x, iv.y, iv.z, iv.w};
            int js[4] = {jv.x, jv.y, jv.z, jv.w};

            float4 pi[4], pj[4];
#pragma unroll
            for (int k = 0; k < 4; k++) {
                pi[k] = __ldg(&g_pos4[is[k]]);
                pj[k] = __ldg(&g_pos4[js[k]]);
            }
#pragma unroll
            for (int k = 0; k < 4; k++)
                do_edge(is[k], js[k], pi[k], pj[k]);
        }
        // remainder edges (E % 4)
        for (int e = (Q << 2) + gtid; e < E; e += gstride) {
            int i = __ldg(&ei[e]);
            int j = __ldg(&ei[E + e]);
            do_edge(i, j, __ldg(&g_pos4[i]), __ldg(&g_pos4[j]));
        }
    }

    grid.sync();

    // ---- Phase C: write forces, bin energies by (sorted) batch ----
    __shared__ float ebins[NUM_GRAPHS];
    int t0 = threadIdx.x;
    if (t0 < NUM_GRAPHS) ebins[t0] = 0.f;
    __syncthreads();

    for (int n = gtid; n < N; n += gstride) {
        float4 a = g_acc[n];
        out[NUM_GRAPHS + 3 * n + 0] = a.x;
        out[NUM_GRAPHS + 3 * n + 1] = a.y;
        out[NUM_GRAPHS + 3 * n + 2] = a.z;
        atomicAdd(&ebins[__ldg(&batch[n])], a.w);
    }
    __syncthreads();
    if (t0 < NUM_GRAPHS) {
        float v = ebins[t0];
        if (v != 0.f) atomicAdd(&out[t0], v);
    }
}

extern "C" void kernel_launch(void* const* d_in, const int* in_sizes, int n_in,
                              void* d_out, int out_size) {
    const float* pos   = (const float*)d_in[0];
    const int*   ei    = (const int*)d_in[1];
    const int*   batch = (const int*)d_in[2];
    float* out = (float*)d_out;

    int N = in_sizes[0] / 3;
    int E = in_sizes[1] / 2;

    // Occupancy-sized cooperative grid (host queries run at capture time only).
    int dev = 0;
    cudaGetDevice(&dev);
    int sm_count = 148;
    cudaDeviceGetAttribute(&sm_count, cudaDevAttrMultiProcessorCount, dev);
    int blocks_per_sm = 1;
    cudaOccupancyMaxActiveBlocksPerMultiprocessor(&blocks_per_sm, fused_kernel,
                                                  NTHREADS, 0);
    int nblocks = sm_count * (blocks_per_sm > 0 ? blocks_per_sm : 1);

    cudaLaunchConfig_t cfg = {};
    cfg.gridDim = dim3(nblocks);
    cfg.blockDim = dim3(NTHREADS);
    cfg.dynamicSmemBytes = 0;
    cfg.stream = 0;
    cudaLaunchAttribute attr[1];
    attr[0].id = cudaLaunchAttributeCooperative;
    attr[0].val.cooperative = 1;
    cfg.attrs = attr;
    cfg.numAttrs = 1;
    cudaLaunchKernelEx(&cfg, fused_kernel, pos, ei, batch, out, N, E);
}

// round 10
// speedup vs baseline: 1.2317x; 1.1900x over previous
#include <cuda_runtime.h>
#include <cstdint>

// Harmonic lattice potential — R9: revert to proven R3 structure.
//   inputs: pos (N,3) f32, edge_index (2,E) int32, batch (N,) int32 (sorted)
//   output: energy (64,) f32 ++ forces (N,3) f32
//
// Evidence across R2-R8: exact-fit 4-edges/thread edge kernel = LSU issue
// floor (~4.5 LSU ops/edge ~ 49us). Grid-stride (R2/R7/R8), 8 edges/thread
// (R6), PDL (R4), prep slimming (R5), and fusion (R7/R8) ALL regressed.
// R9 = R3 with 256-thread prep/finalize blocks (R1 data: 256t prep was
// ~0.5us faster than 128t).

#define R0F 1.0f
#define NUM_GRAPHS 64
#define MAXN 131072

__device__ float4 g_acc[MAXN];    // force.xyz + energy.w accumulator
__device__ float4 g_pos4[MAXN];   // packed positions

__device__ __forceinline__ void red_add_v4(float4* addr, float a, float b, float c, float d) {
    asm volatile("red.global.add.v4.f32 [%0], {%1, %2, %3, %4};"
                 :: "l"(addr), "f"(a), "f"(b), "f"(c), "f"(d));
}

__global__ void prep_kernel(const float* __restrict__ pos, float* __restrict__ out, int N) {
    int t = blockIdx.x * blockDim.x + threadIdx.x;
    if (t < N) {
        g_acc[t]  = make_float4(0.f, 0.f, 0.f, 0.f);
        g_pos4[t] = make_float4(__ldg(&pos[3 * t]), __ldg(&pos[3 * t + 1]),
                                __ldg(&pos[3 * t + 2]), 0.f);
    }
    if (t < NUM_GRAPHS) out[t] = 0.f;   // zero energy slots (d_out poisoned)
}

// Vector path: E % 4 == 0. One quad (4 edges) per thread, exact grid.
__global__ void __launch_bounds__(256)
edge_vec_kernel(const int4* __restrict__ ia, const int4* __restrict__ ja, int Q) {
    int q = blockIdx.x * blockDim.x + threadIdx.x;
    if (q >= Q) return;

    int4 iv = __ldg(&ia[q]);
    int4 jv = __ldg(&ja[q]);
    int is[4] = {iv.x, iv.y, iv.z, iv.w};
    int js[4] = {jv.x, jv.y, jv.z, jv.w};

    float4 pi[4], pj[4];
#pragma unroll
    for (int k = 0; k < 4; k++) {
        pi[k] = __ldg(&g_pos4[is[k]]);
        pj[k] = __ldg(&g_pos4[js[k]]);
    }

#pragma unroll
    for (int k = 0; k < 4; k++) {
        float dx = pi[k].x - pj[k].x;
        float dy = pi[k].y - pj[k].y;
        float dz = pi[k].z - pj[k].z;
        float dd = fmaf(dx, dx, fmaf(dy, dy, dz * dz));
        float rinv = rsqrtf(fmaxf(dd, 1e-40f));
        float d = dd * rinv;                  // = sqrt(dd); 0 when dd==0
        float delta = d - R0F;                // K = 1
        float e = 0.5f * delta * delta;
        float s = delta * rinv;               // dx==0 when dd==0 -> force 0
        float fx = s * dx, fy = s * dy, fz = s * dz;

        red_add_v4(&g_acc[is[k]], -fx, -fy, -fz, e);
        red_add_v4(&g_acc[js[k]],  fx,  fy,  fz, 0.f);
    }
}

// Scalar fallback (E % 4 != 0 — not expected for this dataset).
__global__ void edge_scalar_kernel(const int* __restrict__ ei, int E) {
    int e = blockIdx.x * blockDim.x + threadIdx.x;
    if (e >= E) return;
    int i = __ldg(&ei[e]);
    int j = __ldg(&ei[E + e]);
    float4 pi = __ldg(&g_pos4[i]);
    float4 pj = __ldg(&g_pos4[j]);
    float dx = pi.x - pj.x, dy = pi.y - pj.y, dz = pi.z - pj.z;
    float dd = fmaf(dx, dx, fmaf(dy, dy, dz * dz));
    float rinv = rsqrtf(fmaxf(dd, 1e-40f));
    float d = dd * rinv;
    float delta = d - R0F;
    float e2 = 0.5f * delta * delta;
    float s = delta * rinv;
    float fx = s * dx, fy = s * dy, fz = s * dz;
    red_add_v4(&g_acc[i], -fx, -fy, -fz, e2);
    red_add_v4(&g_acc[j],  fx,  fy,  fz, 0.f);
}

__global__ void finalize_kernel(float* __restrict__ out,
                                const int* __restrict__ batch, int N) {
    __shared__ float ebins[NUM_GRAPHS];
    int t = threadIdx.x;
    if (t < NUM_GRAPHS) ebins[t] = 0.f;
    __syncthreads();

    int n = blockIdx.x * blockDim.x + t;
    if (n < N) {
        float4 a = g_acc[n];
        out[NUM_GRAPHS + 3 * n + 0] = a.x;
        out[NUM_GRAPHS + 3 * n + 1] = a.y;
        out[NUM_GRAPHS + 3 * n + 2] = a.z;
        atomicAdd(&ebins[__ldg(&batch[n])], a.w);   // sorted batch: ~1 bin per block
    }
    __syncthreads();
    if (t < NUM_GRAPHS) {
        float v = ebins[t];
        if (v != 0.f) atomicAdd(&out[t], v);
    }
}

extern "C" void kernel_launch(void* const* d_in, const int* in_sizes, int n_in,
                              void* d_out, int out_size) {
    const float* pos   = (const float*)d_in[0];
    const int*   ei    = (const int*)d_in[1];
    const int*   batch = (const int*)d_in[2];
    float* out = (float*)d_out;

    int N = in_sizes[0] / 3;
    int E = in_sizes[1] / 2;

    {
        int threads = 256;
        int blocks  = (N + threads - 1) / threads;
        prep_kernel<<<blocks, threads>>>(pos, out, N);
    }
    if ((E & 3) == 0) {
        int Q = E >> 2;
        int threads = 256;
        int blocks  = (Q + threads - 1) / threads;
        edge_vec_kernel<<<blocks, threads>>>((const int4*)ei, (const int4*)(ei + E), Q);
    } else {
        int threads = 256;
        int blocks  = (E + threads - 1) / threads;
        edge_scalar_kernel<<<blocks, threads>>>(ei, E);
    }
    {
        int threads = 256;
        int blocks  = (N + threads - 1) / threads;
        finalize_kernel<<<blocks, threads>>>(out, batch, N);
    }
}

// round 12
// speedup vs baseline: 1.3227x; 1.0739x over previous
#include <cuda_runtime.h>
#include <cstdint>

// Harmonic lattice potential — R10: exact R3 configuration (measured best 60.1us).
//   inputs: pos (N,3) f32, edge_index (2,E) int32, batch (N,) int32 (sorted)
//   output: energy (64,) f32 ++ forces (N,3) f32
//
// Final model: edge kernel is at its structural floor (~4.7 cyc/edge/SM:
// 2 random LDG.128 gathers + 2 spread RED.128 per edge). All structural
// variants regressed (grid-stride R2/R7/R8, 8 edges/thread R6, PDL R4,
// prep slimming R5, fusion R7/R8, 256t wrappers R9). Run-to-run spread of
// this configuration is ~60-66us (NAT DVFS). R10 == R3 byte-for-byte.

#define R0F 1.0f
#define NUM_GRAPHS 64
#define MAXN 131072

__device__ float4 g_acc[MAXN];    // force.xyz + energy.w accumulator
__device__ float4 g_pos4[MAXN];   // packed positions

__device__ __forceinline__ void red_add_v4(float4* addr, float a, float b, float c, float d) {
    asm volatile("red.global.add.v4.f32 [%0], {%1, %2, %3, %4};"
                 :: "l"(addr), "f"(a), "f"(b), "f"(c), "f"(d));
}

__global__ void prep_kernel(const float* __restrict__ pos, float* __restrict__ out, int N) {
    int t = blockIdx.x * blockDim.x + threadIdx.x;
    if (t < N) {
        g_acc[t]  = make_float4(0.f, 0.f, 0.f, 0.f);
        g_pos4[t] = make_float4(__ldg(&pos[3 * t]), __ldg(&pos[3 * t + 1]),
                                __ldg(&pos[3 * t + 2]), 0.f);
    }
    if (t < NUM_GRAPHS) out[t] = 0.f;   // zero energy slots (d_out poisoned)
}

// Vector path: E % 4 == 0. One quad (4 edges) per thread, exact grid.
__global__ void __launch_bounds__(256)
edge_vec_kernel(const int4* __restrict__ ia, const int4* __restrict__ ja, int Q) {
    int q = blockIdx.x * blockDim.x + threadIdx.x;
    if (q >= Q) return;

    int4 iv = __ldg(&ia[q]);
    int4 jv = __ldg(&ja[q]);
    int is[4] = {iv.x, iv.y, iv.z, iv.w};
    int js[4] = {jv.x, jv.y, jv.z, jv.w};

    float4 pi[4], pj[4];
#pragma unroll
    for (int k = 0; k < 4; k++) {
        pi[k] = __ldg(&g_pos4[is[k]]);
        pj[k] = __ldg(&g_pos4[js[k]]);
    }

#pragma unroll
    for (int k = 0; k < 4; k++) {
        float dx = pi[k].x - pj[k].x;
        float dy = pi[k].y - pj[k].y;
        float dz = pi[k].z - pj[k].z;
        float dd = fmaf(dx, dx, fmaf(dy, dy, dz * dz));
        float rinv = rsqrtf(fmaxf(dd, 1e-40f));
        float d = dd * rinv;                  // = sqrt(dd); 0 when dd==0
        float delta = d - R0F;                // K = 1
        float e = 0.5f * delta * delta;
        float s = delta * rinv;               // dx==0 when dd==0 -> force 0
        float fx = s * dx, fy = s * dy, fz = s * dz;

        red_add_v4(&g_acc[is[k]], -fx, -fy, -fz, e);
        red_add_v4(&g_acc[js[k]],  fx,  fy,  fz, 0.f);
    }
}

// Scalar fallback (E % 4 != 0 — not expected for this dataset).
__global__ void edge_scalar_kernel(const int* __restrict__ ei, int E) {
    int e = blockIdx.x * blockDim.x + threadIdx.x;
    if (e >= E) return;
    int i = __ldg(&ei[e]);
    int j = __ldg(&ei[E + e]);
    float4 pi = __ldg(&g_pos4[i]);
    float4 pj = __ldg(&g_pos4[j]);
    float dx = pi.x - pj.x, dy = pi.y - pj.y, dz = pi.z - pj.z;
    float dd = fmaf(dx, dx, fmaf(dy, dy, dz * dz));
    float rinv = rsqrtf(fmaxf(dd, 1e-40f));
    float d = dd * rinv;
    float delta = d - R0F;
    float e2 = 0.5f * delta * delta;
    float s = delta * rinv;
    float fx = s * dx, fy = s * dy, fz = s * dz;
    red_add_v4(&g_acc[i], -fx, -fy, -fz, e2);
    red_add_v4(&g_acc[j],  fx,  fy,  fz, 0.f);
}

__global__ void finalize_kernel(float* __restrict__ out,
                                const int* __restrict__ batch, int N) {
    __shared__ float ebins[NUM_GRAPHS];
    int t = threadIdx.x;
    if (t < NUM_GRAPHS) ebins[t] = 0.f;
    __syncthreads();

    int n = blockIdx.x * blockDim.x + t;
    if (n < N) {
        float4 a = g_acc[n];
        out[NUM_GRAPHS + 3 * n + 0] = a.x;
        out[NUM_GRAPHS + 3 * n + 1] = a.y;
        out[NUM_GRAPHS + 3 * n + 2] = a.z;
        atomicAdd(&ebins[__ldg(&batch[n])], a.w);   // sorted batch: ~1 bin per block
    }
    __syncthreads();
    if (t < NUM_GRAPHS) {
        float v = ebins[t];
        if (v != 0.f) atomicAdd(&out[t], v);
    }
}

extern "C" void kernel_launch(void* const* d_in, const int* in_sizes, int n_in,
                              void* d_out, int out_size) {
    const float* pos   = (const float*)d_in[0];
    const int*   ei    = (const int*)d_in[1];
    const int*   batch = (const int*)d_in[2];
    float* out = (float*)d_out;

    int N = in_sizes[0] / 3;
    int E = in_sizes[1] / 2;

    {
        int threads = 128;
        int blocks  = (N + threads - 1) / threads;
        prep_kernel<<<blocks, threads>>>(pos, out, N);
    }
    if ((E & 3) == 0) {
        int Q = E >> 2;
        int threads = 256;
        int blocks  = (Q + threads - 1) / threads;
        edge_vec_kernel<<<blocks, threads>>>((const int4*)ei, (const int4*)(ei + E), Q);
    } else {
        int threads = 256;
        int blocks  = (E + threads - 1) / threads;
        edge_scalar_kernel<<<blocks, threads>>>(ei, E);
    }
    {
        int threads = 128;
        int blocks  = (N + threads - 1) / threads;
        finalize_kernel<<<blocks, threads>>>(out, batch, N);
    }
}

// round 13
// speedup vs baseline: 1.3574x; 1.0262x over previous
#include <cuda_runtime.h>
#include <cstdint>

// Harmonic lattice potential — R12: R3 structure, edge kernel at 128-thread CTAs.
//   inputs: pos (N,3) f32, edge_index (2,E) int32, batch (N,) i32 (sorted)
//   output: energy (64,) f32 ++ forces (N,3) f32
//
// Rationale: edge kernel is at its LSU issue floor (~4.7 cyc/edge/SM). The
// only untested overhead is the wave tail: 3125x256t CTAs = 3.52 waves with a
// 52%-full last wave. 128t CTAs halve the tail quantum (6250 CTAs, 13 CTAs/SM
// = 52 warps) with byte-identical per-thread code. Everything else == R3
// (measured best 60.1us; all structural variants R2/R4-R9 regressed).

#define R0F 1.0f
#define NUM_GRAPHS 64
#define MAXN 131072

__device__ float4 g_acc[MAXN];    // force.xyz + energy.w accumulator
__device__ float4 g_pos4[MAXN];   // packed positions

__device__ __forceinline__ void red_add_v4(float4* addr, float a, float b, float c, float d) {
    asm volatile("red.global.add.v4.f32 [%0], {%1, %2, %3, %4};"
                 :: "l"(addr), "f"(a), "f"(b), "f"(c), "f"(d));
}

__global__ void prep_kernel(const float* __restrict__ pos, float* __restrict__ out, int N) {
    int t = blockIdx.x * blockDim.x + threadIdx.x;
    if (t < N) {
        g_acc[t]  = make_float4(0.f, 0.f, 0.f, 0.f);
        g_pos4[t] = make_float4(__ldg(&pos[3 * t]), __ldg(&pos[3 * t + 1]),
                                __ldg(&pos[3 * t + 2]), 0.f);
    }
    if (t < NUM_GRAPHS) out[t] = 0.f;   // zero energy slots (d_out poisoned)
}

// Vector path: E % 4 == 0. One quad (4 edges) per thread, exact grid, 128t CTAs.
__global__ void __launch_bounds__(128)
edge_vec_kernel(const int4* __restrict__ ia, const int4* __restrict__ ja, int Q) {
    int q = blockIdx.x * blockDim.x + threadIdx.x;
    if (q >= Q) return;

    int4 iv = __ldg(&ia[q]);
    int4 jv = __ldg(&ja[q]);
    int is[4] = {iv.x, iv.y, iv.z, iv.w};
    int js[4] = {jv.x, jv.y, jv.z, jv.w};

    float4 pi[4], pj[4];
#pragma unroll
    for (int k = 0; k < 4; k++) {
        pi[k] = __ldg(&g_pos4[is[k]]);
        pj[k] = __ldg(&g_pos4[js[k]]);
    }

#pragma unroll
    for (int k = 0; k < 4; k++) {
        float dx = pi[k].x - pj[k].x;
        float dy = pi[k].y - pj[k].y;
        float dz = pi[k].z - pj[k].z;
        float dd = fmaf(dx, dx, fmaf(dy, dy, dz * dz));
        float rinv = rsqrtf(fmaxf(dd, 1e-40f));
        float d = dd * rinv;                  // = sqrt(dd); 0 when dd==0
        float delta = d - R0F;                // K = 1
        float e = 0.5f * delta * delta;
        float s = delta * rinv;               // dx==0 when dd==0 -> force 0
        float fx = s * dx, fy = s * dy, fz = s * dz;

        red_add_v4(&g_acc[is[k]], -fx, -fy, -fz, e);
        red_add_v4(&g_acc[js[k]],  fx,  fy,  fz, 0.f);
    }
}

// Scalar fallback (E % 4 != 0 — not expected for this dataset).
__global__ void edge_scalar_kernel(const int* __restrict__ ei, int E) {
    int e = blockIdx.x * blockDim.x + threadIdx.x;
    if (e >= E) return;
    int i = __ldg(&ei[e]);
    int j = __ldg(&ei[E + e]);
    float4 pi = __ldg(&g_pos4[i]);
    float4 pj = __ldg(&g_pos4[j]);
    float dx = pi.x - pj.x, dy = pi.y - pj.y, dz = pi.z - pj.z;
    float dd = fmaf(dx, dx, fmaf(dy, dy, dz * dz));
    float rinv = rsqrtf(fmaxf(dd, 1e-40f));
    float d = dd * rinv;
    float delta = d - R0F;
    float e2 = 0.5f * delta * delta;
    float s = delta * rinv;
    float fx = s * dx, fy = s * dy, fz = s * dz;
    red_add_v4(&g_acc[i], -fx, -fy, -fz, e2);
    red_add_v4(&g_acc[j],  fx,  fy,  fz, 0.f);
}

__global__ void finalize_kernel(float* __restrict__ out,
                                const int* __restrict__ batch, int N) {
    __shared__ float ebins[NUM_GRAPHS];
    int t = threadIdx.x;
    if (t < NUM_GRAPHS) ebins[t] = 0.f;
    __syncthreads();

    int n = blockIdx.x * blockDim.x + t;
    if (n < N) {
        float4 a = g_acc[n];
        out[NUM_GRAPHS + 3 * n + 0] = a.x;
        out[NUM_GRAPHS + 3 * n + 1] = a.y;
        out[NUM_GRAPHS + 3 * n + 2] = a.z;
        atomicAdd(&ebins[__ldg(&batch[n])], a.w);   // sorted batch: ~1 bin per block
    }
    __syncthreads();
    if (t < NUM_GRAPHS) {
        float v = ebins[t];
        if (v != 0.f) atomicAdd(&out[t], v);
    }
}

extern "C" void kernel_launch(void* const* d_in, const int* in_sizes, int n_in,
                              void* d_out, int out_size) {
    const float* pos   = (const float*)d_in[0];
    const int*   ei    = (const int*)d_in[1];
    const int*   batch = (const int*)d_in[2];
    float* out = (float*)d_out;

    int N = in_sizes[0] / 3;
    int E = in_sizes[1] / 2;

    {
        int threads = 128;
        int blocks  = (N + threads - 1) / threads;
        prep_kernel<<<blocks, threads>>>(pos, out, N);
    }
    if ((E & 3) == 0) {
        int Q = E >> 2;
        int threads = 128;
        int blocks  = (Q + threads - 1) / threads;
        edge_vec_kernel<<<blocks, threads>>>((const int4*)ei, (const int4*)(ei + E), Q);
    } else {
        int threads = 128;
        int blocks  = (E + threads - 1) / threads;
        edge_scalar_kernel<<<blocks, threads>>>(ei, E);
    }
    {
        int threads = 128;
        int blocks  = (N + threads - 1) / threads;
        finalize_kernel<<<blocks, threads>>>(out, batch, N);
    }
}

// round 14
// speedup vs baseline: 1.3581x; 1.0005x over previous
#include <cuda_runtime.h>
#include <cstdint>

// Harmonic lattice potential — R13: R12 structure, edge kernel at 64-thread CTAs.
//   inputs: pos (N,3) f32, edge_index (2,E) int32, batch (N,) i32 (sorted)
//   output: energy (64,) f32 ++ forces (N,3) f32
//
// R12 (128t edge CTAs) won: 60.1 -> 59.9. Same axis, one notch finer:
// 64t edge CTAs -> 32 CTAs/SM cap x 2 warps = 64 warps/SM (full occupancy,
// was 52) + 2x finer tail quantum (12500 CTAs). Edge kernel has no
// syncthreads/smem so small CTAs are free. Per-thread SASS unchanged
// (exact-fit, 4 edges/thread — the proven floor configuration).

#define R0F 1.0f
#define NUM_GRAPHS 64
#define MAXN 131072

__device__ float4 g_acc[MAXN];    // force.xyz + energy.w accumulator
__device__ float4 g_pos4[MAXN];   // packed positions

__device__ __forceinline__ void red_add_v4(float4* addr, float a, float b, float c, float d) {
    asm volatile("red.global.add.v4.f32 [%0], {%1, %2, %3, %4};"
                 :: "l"(addr), "f"(a), "f"(b), "f"(c), "f"(d));
}

__global__ void prep_kernel(const float* __restrict__ pos, float* __restrict__ out, int N) {
    int t = blockIdx.x * blockDim.x + threadIdx.x;
    if (t < N) {
        g_acc[t]  = make_float4(0.f, 0.f, 0.f, 0.f);
        g_pos4[t] = make_float4(__ldg(&pos[3 * t]), __ldg(&pos[3 * t + 1]),
                                __ldg(&pos[3 * t + 2]), 0.f);
    }
    if (t < NUM_GRAPHS) out[t] = 0.f;   // zero energy slots (d_out poisoned)
}

// Vector path: E % 4 == 0. One quad (4 edges) per thread, exact grid, 64t CTAs.
__global__ void __launch_bounds__(64)
edge_vec_kernel(const int4* __restrict__ ia, const int4* __restrict__ ja, int Q) {
    int q = blockIdx.x * blockDim.x + threadIdx.x;
    if (q >= Q) return;

    int4 iv = __ldg(&ia[q]);
    int4 jv = __ldg(&ja[q]);
    int is[4] = {iv.x, iv.y, iv.z, iv.w};
    int js[4] = {jv.x, jv.y, jv.z, jv.w};

    float4 pi[4], pj[4];
#pragma unroll
    for (int k = 0; k < 4; k++) {
        pi[k] = __ldg(&g_pos4[is[k]]);
        pj[k] = __ldg(&g_pos4[js[k]]);
    }

#pragma unroll
    for (int k = 0; k < 4; k++) {
        float dx = pi[k].x - pj[k].x;
        float dy = pi[k].y - pj[k].y;
        float dz = pi[k].z - pj[k].z;
        float dd = fmaf(dx, dx, fmaf(dy, dy, dz * dz));
        float rinv = rsqrtf(fmaxf(dd, 1e-40f));
        float d = dd * rinv;                  // = sqrt(dd); 0 when dd==0
        float delta = d - R0F;                // K = 1
        float e = 0.5f * delta * delta;
        float s = delta * rinv;               // dx==0 when dd==0 -> force 0
        float fx = s * dx, fy = s * dy, fz = s * dz;

        red_add_v4(&g_acc[is[k]], -fx, -fy, -fz, e);
        red_add_v4(&g_acc[js[k]],  fx,  fy,  fz, 0.f);
    }
}

// Scalar fallback (E % 4 != 0 — not expected for this dataset).
__global__ void edge_scalar_kernel(const int* __restrict__ ei, int E) {
    int e = blockIdx.x * blockDim.x + threadIdx.x;
    if (e >= E) return;
    int i = __ldg(&ei[e]);
    int j = __ldg(&ei[E + e]);
    float4 pi = __ldg(&g_pos4[i]);
    float4 pj = __ldg(&g_pos4[j]);
    float dx = pi.x - pj.x, dy = pi.y - pj.y, dz = pi.z - pj.z;
    float dd = fmaf(dx, dx, fmaf(dy, dy, dz * dz));
    float rinv = rsqrtf(fmaxf(dd, 1e-40f));
    float d = dd * rinv;
    float delta = d - R0F;
    float e2 = 0.5f * delta * delta;
    float s = delta * rinv;
    float fx = s * dx, fy = s * dy, fz = s * dz;
    red_add_v4(&g_acc[i], -fx, -fy, -fz, e2);
    red_add_v4(&g_acc[j],  fx,  fy,  fz, 0.f);
}

__global__ void finalize_kernel(float* __restrict__ out,
                                const int* __restrict__ batch, int N) {
    __shared__ float ebins[NUM_GRAPHS];
    int t = threadIdx.x;
    if (t < NUM_GRAPHS) ebins[t] = 0.f;
    __syncthreads();

    int n = blockIdx.x * blockDim.x + t;
    if (n < N) {
        float4 a = g_acc[n];
        out[NUM_GRAPHS + 3 * n + 0] = a.x;
        out[NUM_GRAPHS + 3 * n + 1] = a.y;
        out[NUM_GRAPHS + 3 * n + 2] = a.z;
        atomicAdd(&ebins[__ldg(&batch[n])], a.w);   // sorted batch: ~1 bin per block
    }
    __syncthreads();
    if (t < NUM_GRAPHS) {
        float v = ebins[t];
        if (v != 0.f) atomicAdd(&out[t], v);
    }
}

extern "C" void kernel_launch(void* const* d_in, const int* in_sizes, int n_in,
                              void* d_out, int out_size) {
    const float* pos   = (const float*)d_in[0];
    const int*   ei    = (const int*)d_in[1];
    const int*   batch = (const int*)d_in[2];
    float* out = (float*)d_out;

    int N = in_sizes[0] / 3;
    int E = in_sizes[1] / 2;

    {
        int threads = 128;
        int blocks  = (N + threads - 1) / threads;
        prep_kernel<<<blocks, threads>>>(pos, out, N);
    }
    if ((E & 3) == 0) {
        int Q = E >> 2;
        int threads = 64;
        int blocks  = (Q + threads - 1) / threads;
        edge_vec_kernel<<<blocks, threads>>>((const int4*)ei, (const int4*)(ei + E), Q);
    } else {
        int threads = 128;
        int blocks  = (E + threads - 1) / threads;
        edge_scalar_kernel<<<blocks, threads>>>(ei, E);
    }
    {
        int threads = 128;
        int blocks  = (N + threads - 1) / threads;
        finalize_kernel<<<blocks, threads>>>(out, batch, N);
    }
}